// round 14
// baseline (speedup 1.0000x reference)
#include <cuda_runtime.h>
#include <cuda_fp16.h>
#include <math.h>
#include <stdint.h>

// Problem constants (fixed-shape problem)
#define NN 100000
#define EEDGES 1600000
#define NEG_SLOPE 0.2f
#define NBLK_SCAN ((NN + 1023) / 1024)   // 98

#define M_TILE 64
#define ASH 136    // halves per A-smem row (136 mod 64: bank = 4r+tig, conflict-free)
#define WTS 136    // halves per WT-smem row

// ---------------------------------------------------------------------------
// Scratch (device globals — allocation-free rule)
// ---------------------------------------------------------------------------
__device__ __align__(16) __half g_feat[(size_t)NN * 128];  // projected features, fp16
__device__ __align__(16) float  g_el[(size_t)NN * 4];      // [N,H]
__device__ __align__(16) float  g_er[(size_t)NN * 4];      // [N,H]
__device__ __align__(16) int    g_srcs[EEDGES];            // src id, dst-sorted
__device__ __align__(16) int    g_cnt[NN];                 // per-dst degree
__device__ __align__(16) int    g_off[NN];                 // offsets (cursor after scatter)
__device__ __align__(16) int    g_bsum[NBLK_SCAN + 32];
__device__ __align__(16) int    g_boff[NBLK_SCAN + 32];
__device__ __align__(16) __half g_WThi[128 * 128];         // W^T hi halves [n][k]
__device__ __align__(16) __half g_WTlo[128 * 128];         // W^T lo halves [n][k]
__device__ __align__(16) float4 g_Wal[128];                // W @ attn_l  [k][4]
__device__ __align__(16) float4 g_War[128];                // W @ attn_r  [k][4]

// ---------------------------------------------------------------------------
// fp16 mma helper (m16n8k16, fp32 accumulate)
// ---------------------------------------------------------------------------
__device__ __forceinline__ void mma_f16(float c[4],
                                        uint32_t a0, uint32_t a1, uint32_t a2, uint32_t a3,
                                        uint32_t b0, uint32_t b1) {
    asm("mma.sync.aligned.m16n8k16.row.col.f32.f16.f16.f32 "
        "{%0,%1,%2,%3},{%4,%5,%6,%7},{%8,%9},{%0,%1,%2,%3};"
        : "+f"(c[0]), "+f"(c[1]), "+f"(c[2]), "+f"(c[3])
        : "r"(a0), "r"(a1), "r"(a2), "r"(a3), "r"(b0), "r"(b1));
}

// ---------------------------------------------------------------------------
// Kernel: split W into transposed fp16 hi/lo arrays (once per launch)
// ---------------------------------------------------------------------------
__global__ void wsplit_kernel(const float* __restrict__ W) {
    int i = blockIdx.x * blockDim.x + threadIdx.x;
    if (i < 128 * 128) {
        int k = i >> 7, n = i & 127;
        float w = W[i];
        __half h = __float2half_rn(w);
        __half l = __float2half_rn(w - __half2float(h));
        g_WThi[n * 128 + k] = h;
        g_WTlo[n * 128 + k] = l;
    }
}

// ---------------------------------------------------------------------------
// Kernel: Wal = W @ attn_l, War = W @ attn_r (128x4 each; 1 block, 128 thr)
// ---------------------------------------------------------------------------
__global__ void wprep_kernel(const float* __restrict__ W,
                             const float* __restrict__ al,
                             const float* __restrict__ ar) {
    __shared__ float sal[128], sar[128];
    int t = threadIdx.x;
    sal[t] = al[t];
    sar[t] = ar[t];
    __syncthreads();
    const float* wr = W + t * 128;
    float4 L = make_float4(0.f, 0.f, 0.f, 0.f);
    float4 R = make_float4(0.f, 0.f, 0.f, 0.f);
#pragma unroll
    for (int h = 0; h < 4; h++) {
        float sl = 0.f, sr = 0.f;
#pragma unroll 8
        for (int d = 0; d < 32; d++) {
            float w = wr[h * 32 + d];
            sl = fmaf(w, sal[h * 32 + d], sl);
            sr = fmaf(w, sar[h * 32 + d], sr);
        }
        (&L.x)[h] = sl;
        (&R.x)[h] = sr;
    }
    g_Wal[t] = L;
    g_War[t] = R;
}

// ---------------------------------------------------------------------------
// Kernel: el/er = features @ Wal/War, exact fp32. One warp per node.
// ---------------------------------------------------------------------------
__global__ void __launch_bounds__(256)
elr_kernel(const float* __restrict__ A, int N) {
    __shared__ float4 sWal[128], sWar[128];
    int tid = threadIdx.x;
    if (tid < 128) { sWal[tid] = g_Wal[tid]; sWar[tid] = g_War[tid]; }
    __syncthreads();

    int warp = (blockIdx.x * blockDim.x + tid) >> 5;
    int lane = tid & 31;
    if (warp >= N) return;

    float4 a = ((const float4*)A)[(size_t)warp * 32 + lane];
    const float* av = &a.x;
    float4 el = make_float4(0.f, 0.f, 0.f, 0.f);
    float4 er = make_float4(0.f, 0.f, 0.f, 0.f);
#pragma unroll
    for (int j = 0; j < 4; j++) {
        float aj = av[j];
        float4 wl = sWal[lane * 4 + j];
        float4 wr = sWar[lane * 4 + j];
        el.x = fmaf(aj, wl.x, el.x); el.y = fmaf(aj, wl.y, el.y);
        el.z = fmaf(aj, wl.z, el.z); el.w = fmaf(aj, wl.w, el.w);
        er.x = fmaf(aj, wr.x, er.x); er.y = fmaf(aj, wr.y, er.y);
        er.z = fmaf(aj, wr.z, er.z); er.w = fmaf(aj, wr.w, er.w);
    }
#pragma unroll
    for (int s = 16; s >= 1; s >>= 1) {
        el.x += __shfl_xor_sync(0xFFFFFFFFu, el.x, s);
        el.y += __shfl_xor_sync(0xFFFFFFFFu, el.y, s);
        el.z += __shfl_xor_sync(0xFFFFFFFFu, el.z, s);
        el.w += __shfl_xor_sync(0xFFFFFFFFu, el.w, s);
        er.x += __shfl_xor_sync(0xFFFFFFFFu, er.x, s);
        er.y += __shfl_xor_sync(0xFFFFFFFFu, er.y, s);
        er.z += __shfl_xor_sync(0xFFFFFFFFu, er.z, s);
        er.w += __shfl_xor_sync(0xFFFFFFFFu, er.w, s);
    }
    if (lane == 0) {
        ((float4*)g_el)[warp] = el;
        ((float4*)g_er)[warp] = er;
    }
}

// ---------------------------------------------------------------------------
// Kernel: zero degree counters
// ---------------------------------------------------------------------------
__global__ void zero_kernel(int n) {
    int i = blockIdx.x * blockDim.x + threadIdx.x;
    if (i < n) g_cnt[i] = 0;
}

// ---------------------------------------------------------------------------
// Kernel: histogram of dst (4 edges per thread, int4 load)
// ---------------------------------------------------------------------------
__global__ void hist_kernel(const int* __restrict__ dst, int E) {
    int e = (blockIdx.x * blockDim.x + threadIdx.x) * 4;
    if (e + 3 < E) {
        int4 d4 = *(const int4*)(dst + e);
        atomicAdd(&g_cnt[d4.x], 1);
        atomicAdd(&g_cnt[d4.y], 1);
        atomicAdd(&g_cnt[d4.z], 1);
        atomicAdd(&g_cnt[d4.w], 1);
    } else {
        for (int k = e; k < E; k++) atomicAdd(&g_cnt[dst[k]], 1);
    }
}

// ---------------------------------------------------------------------------
// Scan A: per-1024-block exclusive scan of g_cnt -> g_off, totals -> g_bsum
// ---------------------------------------------------------------------------
__global__ void scanA_kernel(int N) {
    __shared__ int wtot[8];
    __shared__ int wexcl[8];
    int tid = threadIdx.x;
    int lane = tid & 31;
    int base = blockIdx.x * 1024 + tid * 4;

    int4 c = make_int4(0, 0, 0, 0);
    if (base + 3 < N) {
        c = *(const int4*)(g_cnt + base);
    } else {
        if (base + 0 < N) c.x = g_cnt[base + 0];
        if (base + 1 < N) c.y = g_cnt[base + 1];
        if (base + 2 < N) c.z = g_cnt[base + 2];
        if (base + 3 < N) c.w = g_cnt[base + 3];
    }
    int tsum = c.x + c.y + c.z + c.w;
    int incl = tsum;
#pragma unroll
    for (int s = 1; s < 32; s <<= 1) {
        int v = __shfl_up_sync(0xFFFFFFFFu, incl, s);
        if (lane >= s) incl += v;
    }
    if (lane == 31) wtot[tid >> 5] = incl;
    __syncthreads();
    if (tid == 0) {
        int r = 0;
#pragma unroll
        for (int w = 0; w < 8; w++) { wexcl[w] = r; r += wtot[w]; }
        g_bsum[blockIdx.x] = r;
    }
    __syncthreads();
    int p = wexcl[tid >> 5] + incl - tsum;
    if (base + 0 < N) g_off[base + 0] = p;
    if (base + 1 < N) g_off[base + 1] = p + c.x;
    if (base + 2 < N) g_off[base + 2] = p + c.x + c.y;
    if (base + 3 < N) g_off[base + 3] = p + c.x + c.y + c.z;
}

// ---------------------------------------------------------------------------
// Scan B: exclusive scan of block totals (single block, 128 threads)
// ---------------------------------------------------------------------------
__global__ void scanB_kernel(int nb) {
    __shared__ int wtot[4];
    __shared__ int wexcl[4];
    int t = threadIdx.x;
    int lane = t & 31;
    int v = (t < nb) ? g_bsum[t] : 0;
    int incl = v;
#pragma unroll
    for (int s = 1; s < 32; s <<= 1) {
        int u = __shfl_up_sync(0xFFFFFFFFu, incl, s);
        if (lane >= s) incl += u;
    }
    if (lane == 31) wtot[t >> 5] = incl;
    __syncthreads();
    if (t == 0) {
        int r = 0;
#pragma unroll
        for (int w = 0; w < 4; w++) { wexcl[w] = r; r += wtot[w]; }
    }
    __syncthreads();
    if (t < nb) g_boff[t] = wexcl[t >> 5] + incl - v;
}

// ---------------------------------------------------------------------------
// Kernel: GEMM feat = A @ W via fp16-Markidis (hi/lo, m16n8k16 tensor cores).
// Block: 256 threads (8 warps), tile 64(M) x 128(N), K=128, 8 K-steps.
// A split once at smem-load; W pre-split globally (wsplit), copied to smem.
// Inner loop: pure LDS + 3 MMAs per (mt,nt) per K=16. smem 104.4 KB -> 2/SM.
// ---------------------------------------------------------------------------
__global__ void __launch_bounds__(256, 2)
gemm_kernel(const float* __restrict__ A, int N) {
    extern __shared__ __half smh[];
    __half* A_hi  = smh;                       // [64][ASH]
    __half* A_lo  = smh + 64 * ASH;
    __half* WT_hi = smh + 2 * 64 * ASH;        // [128][WTS]
    __half* WT_lo = WT_hi + 128 * WTS;

    int tid = threadIdx.x;
    int rowBase = blockIdx.x * M_TILE;

    // Copy pre-split W^T (hi/lo) into padded smem, vectorized 16B
    for (int i = tid; i < 128 * 16; i += 256) {
        int n = i >> 4, c = i & 15;
        *(uint4*)(WT_hi + n * WTS + c * 8) = ((const uint4*)g_WThi)[n * 16 + c];
        *(uint4*)(WT_lo + n * WTS + c * 8) = ((const uint4*)g_WTlo)[n * 16 + c];
    }
    // Load A tile, split each element once into hi/lo halves
    for (int i = tid; i < M_TILE * 32; i += 256) {
        int r = i >> 5, c4 = i & 31;
        int gr = rowBase + r;
        float4 v = make_float4(0.f, 0.f, 0.f, 0.f);
        if (gr < N) v = ((const float4*)A)[(size_t)gr * 32 + c4];
        __half hx = __float2half_rn(v.x), hy = __float2half_rn(v.y);
        __half hz = __float2half_rn(v.z), hw = __float2half_rn(v.w);
        __half lx = __float2half_rn(v.x - __half2float(hx));
        __half ly = __float2half_rn(v.y - __half2float(hy));
        __half lz = __float2half_rn(v.z - __half2float(hz));
        __half lw = __float2half_rn(v.w - __half2float(hw));
        int b = r * ASH + c4 * 4;
        *(__half2*)(A_hi + b)     = __halves2half2(hx, hy);
        *(__half2*)(A_hi + b + 2) = __halves2half2(hz, hw);
        *(__half2*)(A_lo + b)     = __halves2half2(lx, ly);
        *(__half2*)(A_lo + b + 2) = __halves2half2(lz, lw);
    }
    __syncthreads();

    int wid  = tid >> 5;
    int lane = tid & 31;
    int grp  = lane >> 2;    // 0..7
    int tig  = lane & 3;     // 0..3
    int warpM = wid >> 2;    // 0..1  (32 rows each)
    int warpN = wid & 3;     // 0..3  (32 cols each)

    float C[2][4][4];
#pragma unroll
    for (int mt = 0; mt < 2; mt++)
#pragma unroll
        for (int nt = 0; nt < 4; nt++)
#pragma unroll
            for (int q = 0; q < 4; q++) C[mt][nt][q] = 0.f;

#pragma unroll
    for (int step = 0; step < 8; step++) {
        int kk = step * 16;

        uint32_t Ah[2][4], Al[2][4];
#pragma unroll
        for (int mt = 0; mt < 2; mt++) {
            int r0 = warpM * 32 + mt * 16 + grp;
            const __half* ph = A_hi + r0 * ASH + kk + 2 * tig;
            const __half* pl = A_lo + r0 * ASH + kk + 2 * tig;
            Ah[mt][0] = *(const uint32_t*)(ph);
            Ah[mt][1] = *(const uint32_t*)(ph + 8 * ASH);
            Ah[mt][2] = *(const uint32_t*)(ph + 8);
            Ah[mt][3] = *(const uint32_t*)(ph + 8 * ASH + 8);
            Al[mt][0] = *(const uint32_t*)(pl);
            Al[mt][1] = *(const uint32_t*)(pl + 8 * ASH);
            Al[mt][2] = *(const uint32_t*)(pl + 8);
            Al[mt][3] = *(const uint32_t*)(pl + 8 * ASH + 8);
        }

        uint32_t Bh[4][2], Bl[4][2];
#pragma unroll
        for (int nt = 0; nt < 4; nt++) {
            int n = warpN * 32 + nt * 8 + grp;
            const __half* bh = WT_hi + n * WTS + kk + 2 * tig;
            const __half* bl = WT_lo + n * WTS + kk + 2 * tig;
            Bh[nt][0] = *(const uint32_t*)(bh);
            Bh[nt][1] = *(const uint32_t*)(bh + 8);
            Bl[nt][0] = *(const uint32_t*)(bl);
            Bl[nt][1] = *(const uint32_t*)(bl + 8);
        }

#pragma unroll
        for (int mt = 0; mt < 2; mt++)
#pragma unroll
            for (int nt = 0; nt < 4; nt++) {
                mma_f16(C[mt][nt], Ah[mt][0], Ah[mt][1], Ah[mt][2], Ah[mt][3],
                        Bh[nt][0], Bh[nt][1]);
                mma_f16(C[mt][nt], Al[mt][0], Al[mt][1], Al[mt][2], Al[mt][3],
                        Bh[nt][0], Bh[nt][1]);
                mma_f16(C[mt][nt], Ah[mt][0], Ah[mt][1], Ah[mt][2], Ah[mt][3],
                        Bl[nt][0], Bl[nt][1]);
            }
    }

    // ---- store feat as fp16 (half2 per c0,c1 pair) ----
    __half2* feat_h2 = (__half2*)g_feat;
#pragma unroll
    for (int mt = 0; mt < 2; mt++) {
        int row0 = rowBase + warpM * 32 + mt * 16 + grp;
#pragma unroll
        for (int nt = 0; nt < 4; nt++) {
            int colh = warpN * 16 + nt * 4 + tig;   // (col / 2)
            if (row0 < N)
                feat_h2[(size_t)row0 * 64 + colh] =
                    __floats2half2_rn(C[mt][nt][0], C[mt][nt][1]);
            if (row0 + 8 < N)
                feat_h2[(size_t)(row0 + 8) * 64 + colh] =
                    __floats2half2_rn(C[mt][nt][2], C[mt][nt][3]);
        }
    }
}

// ---------------------------------------------------------------------------
// Kernel: permute src ids into dst-sorted order.
// ---------------------------------------------------------------------------
__global__ void edge_scatter_kernel(const int* __restrict__ src,
                                    const int* __restrict__ dst,
                                    int E) {
    int e = (blockIdx.x * blockDim.x + threadIdx.x) * 2;
    if (e + 1 < E) {
        int2 s2 = *(const int2*)(src + e);
        int2 d2 = *(const int2*)(dst + e);
        int r0 = atomicAdd(&g_off[d2.x], 1);
        g_srcs[__ldg(&g_boff[d2.x >> 10]) + r0] = s2.x;
        int r1 = atomicAdd(&g_off[d2.y], 1);
        g_srcs[__ldg(&g_boff[d2.y >> 10]) + r1] = s2.y;
    } else if (e < E) {
        int s = src[e];
        int d = dst[e];
        int r = atomicAdd(&g_off[d], 1);
        g_srcs[__ldg(&g_boff[d >> 10]) + r] = s;
    }
}

// ---------------------------------------------------------------------------
// Kernel: gather aggregation. One warp per dst node (4-wide pipelined).
// fp16 feat gather: 8 B per lane per edge (coalesced 256 B/warp).
// ---------------------------------------------------------------------------
__global__ void __launch_bounds__(256)
aggregate_kernel(const float* __restrict__ bias,
                 float* __restrict__ out,
                 int N) {
    int node = (blockIdx.x * blockDim.x + threadIdx.x) >> 5;
    int lane = threadIdx.x & 31;
    if (node >= N) return;

    int cnt = g_cnt[node];
    int off = g_boff[node >> 10] + g_off[node] - cnt;   // segment start (global)
    int h = lane >> 3;

    float er_h = g_er[node * 4 + h];

    float4 acc = make_float4(0.f, 0.f, 0.f, 0.f);
    float den = 0.f;

    const uint2* feat8 = (const uint2*)g_feat;   // 8 B = 4 halves per lane

    int i = 0;
    for (; i + 4 <= cnt; i += 4) {
        int s0 = g_srcs[off + i + 0];
        int s1 = g_srcs[off + i + 1];
        int s2 = g_srcs[off + i + 2];
        int s3 = g_srcs[off + i + 3];
        float e0 = __ldg(&g_el[s0 * 4 + h]) + er_h;
        float e1 = __ldg(&g_el[s1 * 4 + h]) + er_h;
        float e2 = __ldg(&g_el[s2 * 4 + h]) + er_h;
        float e3 = __ldg(&g_el[s3 * 4 + h]) + er_h;
        uint2 r0 = feat8[(size_t)s0 * 32 + lane];
        uint2 r1 = feat8[(size_t)s1 * 32 + lane];
        uint2 r2 = feat8[(size_t)s2 * 32 + lane];
        uint2 r3 = feat8[(size_t)s3 * 32 + lane];
        e0 = e0 > 0.f ? e0 : NEG_SLOPE * e0;
        e1 = e1 > 0.f ? e1 : NEG_SLOPE * e1;
        e2 = e2 > 0.f ? e2 : NEG_SLOPE * e2;
        e3 = e3 > 0.f ? e3 : NEG_SLOPE * e3;
        float w0 = __expf(e0), w1 = __expf(e1), w2 = __expf(e2), w3 = __expf(e3);
        den += (w0 + w1) + (w2 + w3);
        float2 a0 = __half22float2(*(__half2*)&r0.x);
        float2 b0 = __half22float2(*(__half2*)&r0.y);
        float2 a1 = __half22float2(*(__half2*)&r1.x);
        float2 b1 = __half22float2(*(__half2*)&r1.y);
        float2 a2 = __half22float2(*(__half2*)&r2.x);
        float2 b2 = __half22float2(*(__half2*)&r2.y);
        float2 a3 = __half22float2(*(__half2*)&r3.x);
        float2 b3 = __half22float2(*(__half2*)&r3.y);
        acc.x = fmaf(w0, a0.x, acc.x); acc.y = fmaf(w0, a0.y, acc.y);
        acc.z = fmaf(w0, b0.x, acc.z); acc.w = fmaf(w0, b0.y, acc.w);
        acc.x = fmaf(w1, a1.x, acc.x); acc.y = fmaf(w1, a1.y, acc.y);
        acc.z = fmaf(w1, b1.x, acc.z); acc.w = fmaf(w1, b1.y, acc.w);
        acc.x = fmaf(w2, a2.x, acc.x); acc.y = fmaf(w2, a2.y, acc.y);
        acc.z = fmaf(w2, b2.x, acc.z); acc.w = fmaf(w2, b2.y, acc.w);
        acc.x = fmaf(w3, a3.x, acc.x); acc.y = fmaf(w3, a3.y, acc.y);
        acc.z = fmaf(w3, b3.x, acc.z); acc.w = fmaf(w3, b3.y, acc.w);
    }
    for (; i < cnt; i++) {
        int s0 = g_srcs[off + i];
        float e0 = __ldg(&g_el[s0 * 4 + h]) + er_h;
        e0 = e0 > 0.f ? e0 : NEG_SLOPE * e0;
        float w0 = __expf(e0);
        uint2 r0 = feat8[(size_t)s0 * 32 + lane];
        float2 a0 = __half22float2(*(__half2*)&r0.x);
        float2 b0 = __half22float2(*(__half2*)&r0.y);
        den += w0;
        acc.x = fmaf(w0, a0.x, acc.x); acc.y = fmaf(w0, a0.y, acc.y);
        acc.z = fmaf(w0, b0.x, acc.z); acc.w = fmaf(w0, b0.y, acc.w);
    }

    float inv = __fdividef(1.0f, fmaxf(den, 1e-9f));
    float4 bvec = ((const float4*)bias)[lane];
    acc.x = acc.x * inv + bvec.x;
    acc.y = acc.y * inv + bvec.y;
    acc.z = acc.z * inv + bvec.z;
    acc.w = acc.w * inv + bvec.w;
    acc.x = acc.x > 0.f ? acc.x : expm1f(acc.x);
    acc.y = acc.y > 0.f ? acc.y : expm1f(acc.y);
    acc.z = acc.z > 0.f ? acc.z : expm1f(acc.z);
    acc.w = acc.w > 0.f ? acc.w : expm1f(acc.w);
    __stcs(&((float4*)out)[(size_t)node * 32 + lane], acc);
}

// ---------------------------------------------------------------------------
// Launcher. 3 streams: default = wsplit+gemm, s2 = sort chain, s3 = wprep+elr.
// Submission order keeps gemm the 4th kernel (ncu profiles slot #4).
// ---------------------------------------------------------------------------
extern "C" void kernel_launch(void* const* d_in, const int* in_sizes, int n_in,
                              void* d_out, int out_size) {
    const float* features = (const float*)d_in[0];
    const int*   src      = (const int*)d_in[1];
    const int*   dst      = (const int*)d_in[2];
    const float* W        = (const float*)d_in[3];
    const float* attn_l   = (const float*)d_in[4];
    const float* attn_r   = (const float*)d_in[5];
    const float* bias     = (const float*)d_in[6];
    float*       out      = (float*)d_out;

    int N = in_sizes[0] / 128;   // 100000
    int E = in_sizes[1];         // 1600000
    int nb = (N + 1023) / 1024;  // scan blocks

    const int GEMM_SMEM = (2 * 64 * ASH + 2 * 128 * WTS) * 2;  // 104448 bytes

    static cudaStream_t s2 = nullptr, s3 = nullptr;
    static cudaEvent_t evFork = nullptr, evJoin2 = nullptr, evJoin3 = nullptr;
    if (!s2) {
        cudaStreamCreateWithFlags(&s2, cudaStreamNonBlocking);
        cudaStreamCreateWithFlags(&s3, cudaStreamNonBlocking);
        cudaEventCreateWithFlags(&evFork, cudaEventDisableTiming);
        cudaEventCreateWithFlags(&evJoin2, cudaEventDisableTiming);
        cudaEventCreateWithFlags(&evJoin3, cudaEventDisableTiming);
        cudaFuncSetAttribute(gemm_kernel, cudaFuncAttributeMaxDynamicSharedMemorySize, GEMM_SMEM);
    }

    // fork side streams from the (capture) default stream
    cudaEventRecord(evFork, 0);
    cudaStreamWaitEvent(s2, evFork, 0);
    cudaStreamWaitEvent(s3, evFork, 0);

    // 1 (default): W split (precedes gemm on same stream)
    wsplit_kernel<<<64, 256>>>(W);

    // 2-3 (s2): zero + hist
    zero_kernel<<<(N + 255) / 256, 256, 0, s2>>>(N);
    hist_kernel<<<(E / 4 + 255) / 256, 256, 0, s2>>>(dst, E);

    // 4 (default): fp16-Markidis tensor-core GEMM — profiled by ncu
    gemm_kernel<<<(N + M_TILE - 1) / M_TILE, 256, GEMM_SMEM>>>(features, N);

    // 5-6 (s3): wprep + elr (exact fp32 logits, independent of gemm)
    wprep_kernel<<<1, 128, 0, s3>>>(W, attn_l, attn_r);
    elr_kernel<<<(N + 7) / 8, 256, 0, s3>>>(features, N);
    cudaEventRecord(evJoin3, s3);

    // 7-9 (s2): scanA + scanB + scatter
    scanA_kernel<<<nb, 256, 0, s2>>>(N);
    scanB_kernel<<<1, 128, 0, s2>>>(nb);
    edge_scatter_kernel<<<(E / 2 + 255) / 256, 256, 0, s2>>>(src, dst, E);
    cudaEventRecord(evJoin2, s2);

    // join all, then aggregate
    cudaStreamWaitEvent(0, evJoin2, 0);
    cudaStreamWaitEvent(0, evJoin3, 0);
    aggregate_kernel<<<(N + 7) / 8, 256>>>(bias, out, N);
}

// round 16
// speedup vs baseline: 1.3218x; 1.3218x over previous
#include <cuda_runtime.h>
#include <cuda_fp16.h>
#include <math.h>
#include <stdint.h>

// Problem constants (fixed-shape problem)
#define NN 100000
#define EEDGES 1600000
#define NEG_SLOPE 0.2f
#define NBLK_SCAN ((NN + 1023) / 1024)   // 98

#define M_TILE 64
#define ASH 136    // halves per A-smem row
#define WTS 136    // halves per WT-smem row

// ---------------------------------------------------------------------------
// Scratch (device globals — allocation-free rule)
// ---------------------------------------------------------------------------
__device__ __align__(16) __half g_feat[(size_t)NN * 128];  // projected features, fp16
__device__ __align__(16) float  g_el[(size_t)NN * 4];      // [N,H]
__device__ __align__(16) float  g_er[(size_t)NN * 4];      // [N,H]
__device__ __align__(16) int    g_srcs[EEDGES];            // src id, dst-sorted
__device__ __align__(16) int    g_cnt[NN];                 // per-dst degree
__device__ __align__(16) int    g_off[NN];                 // offsets (cursor after scatter)
__device__ __align__(16) int    g_bsum[NBLK_SCAN + 32];
__device__ __align__(16) int    g_boff[NBLK_SCAN + 32];
__device__ __align__(16) __half g_WThi[128 * 128];         // W^T hi halves [n][k]
__device__ __align__(16) __half g_WTlo[128 * 128];         // W^T lo halves [n][k]

// ---------------------------------------------------------------------------
// fp16 mma helper (m16n8k16, fp32 accumulate)
// ---------------------------------------------------------------------------
__device__ __forceinline__ void mma_f16(float c[4],
                                        uint32_t a0, uint32_t a1, uint32_t a2, uint32_t a3,
                                        uint32_t b0, uint32_t b1) {
    asm("mma.sync.aligned.m16n8k16.row.col.f32.f16.f16.f32 "
        "{%0,%1,%2,%3},{%4,%5,%6,%7},{%8,%9},{%0,%1,%2,%3};"
        : "+f"(c[0]), "+f"(c[1]), "+f"(c[2]), "+f"(c[3])
        : "r"(a0), "r"(a1), "r"(a2), "r"(a3), "r"(b0), "r"(b1));
}

// ---------------------------------------------------------------------------
// Kernel: split W into transposed fp16 hi/lo arrays (once per launch)
// ---------------------------------------------------------------------------
__global__ void wsplit_kernel(const float* __restrict__ W) {
    int i = blockIdx.x * blockDim.x + threadIdx.x;
    if (i < 128 * 128) {
        int k = i >> 7, n = i & 127;
        float w = W[i];
        __half h = __float2half_rn(w);
        __half l = __float2half_rn(w - __half2float(h));
        g_WThi[n * 128 + k] = h;
        g_WTlo[n * 128 + k] = l;
    }
}

// ---------------------------------------------------------------------------
// Kernel: zero degree counters
// ---------------------------------------------------------------------------
__global__ void zero_kernel(int n) {
    int i = blockIdx.x * blockDim.x + threadIdx.x;
    if (i < n) g_cnt[i] = 0;
}

// ---------------------------------------------------------------------------
// Kernel: histogram of dst (4 edges per thread, int4 load)
// ---------------------------------------------------------------------------
__global__ void hist_kernel(const int* __restrict__ dst, int E) {
    int e = (blockIdx.x * blockDim.x + threadIdx.x) * 4;
    if (e + 3 < E) {
        int4 d4 = *(const int4*)(dst + e);
        atomicAdd(&g_cnt[d4.x], 1);
        atomicAdd(&g_cnt[d4.y], 1);
        atomicAdd(&g_cnt[d4.z], 1);
        atomicAdd(&g_cnt[d4.w], 1);
    } else {
        for (int k = e; k < E; k++) atomicAdd(&g_cnt[dst[k]], 1);
    }
}

// ---------------------------------------------------------------------------
// Scan A: per-1024-block exclusive scan of g_cnt -> g_off, totals -> g_bsum
// ---------------------------------------------------------------------------
__global__ void scanA_kernel(int N) {
    __shared__ int wtot[8];
    __shared__ int wexcl[8];
    int tid = threadIdx.x;
    int lane = tid & 31;
    int base = blockIdx.x * 1024 + tid * 4;

    int4 c = make_int4(0, 0, 0, 0);
    if (base + 3 < N) {
        c = *(const int4*)(g_cnt + base);
    } else {
        if (base + 0 < N) c.x = g_cnt[base + 0];
        if (base + 1 < N) c.y = g_cnt[base + 1];
        if (base + 2 < N) c.z = g_cnt[base + 2];
        if (base + 3 < N) c.w = g_cnt[base + 3];
    }
    int tsum = c.x + c.y + c.z + c.w;
    int incl = tsum;
#pragma unroll
    for (int s = 1; s < 32; s <<= 1) {
        int v = __shfl_up_sync(0xFFFFFFFFu, incl, s);
        if (lane >= s) incl += v;
    }
    if (lane == 31) wtot[tid >> 5] = incl;
    __syncthreads();
    if (tid == 0) {
        int r = 0;
#pragma unroll
        for (int w = 0; w < 8; w++) { wexcl[w] = r; r += wtot[w]; }
        g_bsum[blockIdx.x] = r;
    }
    __syncthreads();
    int p = wexcl[tid >> 5] + incl - tsum;
    if (base + 0 < N) g_off[base + 0] = p;
    if (base + 1 < N) g_off[base + 1] = p + c.x;
    if (base + 2 < N) g_off[base + 2] = p + c.x + c.y;
    if (base + 3 < N) g_off[base + 3] = p + c.x + c.y + c.z;
}

// ---------------------------------------------------------------------------
// Scan B: exclusive scan of block totals (single block, 128 threads)
// ---------------------------------------------------------------------------
__global__ void scanB_kernel(int nb) {
    __shared__ int wtot[4];
    __shared__ int wexcl[4];
    int t = threadIdx.x;
    int lane = t & 31;
    int v = (t < nb) ? g_bsum[t] : 0;
    int incl = v;
#pragma unroll
    for (int s = 1; s < 32; s <<= 1) {
        int u = __shfl_up_sync(0xFFFFFFFFu, incl, s);
        if (lane >= s) incl += u;
    }
    if (lane == 31) wtot[t >> 5] = incl;
    __syncthreads();
    if (t == 0) {
        int r = 0;
#pragma unroll
        for (int w = 0; w < 4; w++) { wexcl[w] = r; r += wtot[w]; }
    }
    __syncthreads();
    if (t < nb) g_boff[t] = wexcl[t >> 5] + incl - v;
}

// ---------------------------------------------------------------------------
// Kernel: GEMM feat = A @ W via fp16-Markidis (hi/lo, m16n8k16 tensor cores),
// with fused el/er epilogue from the fp32 accumulators (head h = warpN).
// Block: 256 threads (8 warps), tile 64(M) x 128(N), K=128, 8 K-steps.
// smem 104.4 KB -> 2 blocks/SM.
// ---------------------------------------------------------------------------
__global__ void __launch_bounds__(256, 2)
gemm_kernel(const float* __restrict__ A,
            const float* __restrict__ attn_l,
            const float* __restrict__ attn_r,
            int N) {
    extern __shared__ __half smh[];
    __half* A_hi  = smh;                       // [64][ASH]
    __half* A_lo  = smh + 64 * ASH;
    __half* WT_hi = smh + 2 * 64 * ASH;        // [128][WTS]
    __half* WT_lo = WT_hi + 128 * WTS;

    int tid = threadIdx.x;
    int rowBase = blockIdx.x * M_TILE;

    // Copy pre-split W^T (hi/lo) into padded smem, vectorized 16B
    for (int i = tid; i < 128 * 16; i += 256) {
        int n = i >> 4, c = i & 15;
        *(uint4*)(WT_hi + n * WTS + c * 8) = ((const uint4*)g_WThi)[n * 16 + c];
        *(uint4*)(WT_lo + n * WTS + c * 8) = ((const uint4*)g_WTlo)[n * 16 + c];
    }
    // Load A tile, split each element once into hi/lo halves
    for (int i = tid; i < M_TILE * 32; i += 256) {
        int r = i >> 5, c4 = i & 31;
        int gr = rowBase + r;
        float4 v = make_float4(0.f, 0.f, 0.f, 0.f);
        if (gr < N) v = ((const float4*)A)[(size_t)gr * 32 + c4];
        __half hx = __float2half_rn(v.x), hy = __float2half_rn(v.y);
        __half hz = __float2half_rn(v.z), hw = __float2half_rn(v.w);
        __half lx = __float2half_rn(v.x - __half2float(hx));
        __half ly = __float2half_rn(v.y - __half2float(hy));
        __half lz = __float2half_rn(v.z - __half2float(hz));
        __half lw = __float2half_rn(v.w - __half2float(hw));
        int b = r * ASH + c4 * 4;
        *(__half2*)(A_hi + b)     = __halves2half2(hx, hy);
        *(__half2*)(A_hi + b + 2) = __halves2half2(hz, hw);
        *(__half2*)(A_lo + b)     = __halves2half2(lx, ly);
        *(__half2*)(A_lo + b + 2) = __halves2half2(lz, lw);
    }
    __syncthreads();

    int wid  = tid >> 5;
    int lane = tid & 31;
    int grp  = lane >> 2;    // 0..7
    int tig  = lane & 3;     // 0..3
    int warpM = wid >> 2;    // 0..1  (32 rows each)
    int warpN = wid & 3;     // 0..3  (32 cols each == head warpN)

    float C[2][4][4];
#pragma unroll
    for (int mt = 0; mt < 2; mt++)
#pragma unroll
        for (int nt = 0; nt < 4; nt++)
#pragma unroll
            for (int q = 0; q < 4; q++) C[mt][nt][q] = 0.f;

#pragma unroll
    for (int step = 0; step < 8; step++) {
        int kk = step * 16;

        uint32_t Ah[2][4], Al[2][4];
#pragma unroll
        for (int mt = 0; mt < 2; mt++) {
            int r0 = warpM * 32 + mt * 16 + grp;
            const __half* ph = A_hi + r0 * ASH + kk + 2 * tig;
            const __half* pl = A_lo + r0 * ASH + kk + 2 * tig;
            Ah[mt][0] = *(const uint32_t*)(ph);
            Ah[mt][1] = *(const uint32_t*)(ph + 8 * ASH);
            Ah[mt][2] = *(const uint32_t*)(ph + 8);
            Ah[mt][3] = *(const uint32_t*)(ph + 8 * ASH + 8);
            Al[mt][0] = *(const uint32_t*)(pl);
            Al[mt][1] = *(const uint32_t*)(pl + 8 * ASH);
            Al[mt][2] = *(const uint32_t*)(pl + 8);
            Al[mt][3] = *(const uint32_t*)(pl + 8 * ASH + 8);
        }

        uint32_t Bh[4][2], Bl[4][2];
#pragma unroll
        for (int nt = 0; nt < 4; nt++) {
            int n = warpN * 32 + nt * 8 + grp;
            const __half* bh = WT_hi + n * WTS + kk + 2 * tig;
            const __half* bl = WT_lo + n * WTS + kk + 2 * tig;
            Bh[nt][0] = *(const uint32_t*)(bh);
            Bh[nt][1] = *(const uint32_t*)(bh + 8);
            Bl[nt][0] = *(const uint32_t*)(bl);
            Bl[nt][1] = *(const uint32_t*)(bl + 8);
        }

#pragma unroll
        for (int mt = 0; mt < 2; mt++)
#pragma unroll
            for (int nt = 0; nt < 4; nt++) {
                mma_f16(C[mt][nt], Ah[mt][0], Ah[mt][1], Ah[mt][2], Ah[mt][3],
                        Bh[nt][0], Bh[nt][1]);
                mma_f16(C[mt][nt], Al[mt][0], Al[mt][1], Al[mt][2], Al[mt][3],
                        Bh[nt][0], Bh[nt][1]);
                mma_f16(C[mt][nt], Ah[mt][0], Ah[mt][1], Ah[mt][2], Ah[mt][3],
                        Bl[nt][0], Bl[nt][1]);
            }
    }

    // ---- store feat as fp16 (half2 per c0,c1 pair) ----
    __half2* feat_h2 = (__half2*)g_feat;
#pragma unroll
    for (int mt = 0; mt < 2; mt++) {
        int row0 = rowBase + warpM * 32 + mt * 16 + grp;
#pragma unroll
        for (int nt = 0; nt < 4; nt++) {
            int colh = warpN * 16 + nt * 4 + tig;   // (col / 2)
            if (row0 < N)
                feat_h2[(size_t)row0 * 64 + colh] =
                    __floats2half2_rn(C[mt][nt][0], C[mt][nt][1]);
            if (row0 + 8 < N)
                feat_h2[(size_t)(row0 + 8) * 64 + colh] =
                    __floats2half2_rn(C[mt][nt][2], C[mt][nt][3]);
        }
    }

    // ---- fused el/er epilogue (head h = warpN), fp32 from accumulators ----
    float alv[4][2], arv[4][2];
#pragma unroll
    for (int nt = 0; nt < 4; nt++) {
        int col = warpN * 32 + nt * 8 + 2 * tig;
        alv[nt][0] = __ldg(&attn_l[col]);
        alv[nt][1] = __ldg(&attn_l[col + 1]);
        arv[nt][0] = __ldg(&attn_r[col]);
        arv[nt][1] = __ldg(&attn_r[col + 1]);
    }

#pragma unroll
    for (int mt = 0; mt < 2; mt++) {
        int row0 = rowBase + warpM * 32 + mt * 16 + grp;
#pragma unroll
        for (int half = 0; half < 2; half++) {
            float pl = 0.f, pr = 0.f;
#pragma unroll
            for (int nt = 0; nt < 4; nt++) {
                float c0 = C[mt][nt][half * 2 + 0];
                float c1 = C[mt][nt][half * 2 + 1];
                pl = fmaf(c0, alv[nt][0], fmaf(c1, alv[nt][1], pl));
                pr = fmaf(c0, arv[nt][0], fmaf(c1, arv[nt][1], pr));
            }
            pl += __shfl_xor_sync(0xFFFFFFFFu, pl, 1);
            pl += __shfl_xor_sync(0xFFFFFFFFu, pl, 2);
            pr += __shfl_xor_sync(0xFFFFFFFFu, pr, 1);
            pr += __shfl_xor_sync(0xFFFFFFFFu, pr, 2);
            int row = row0 + half * 8;
            if (tig == 0 && row < N) {
                g_el[row * 4 + warpN] = pl;
                g_er[row * 4 + warpN] = pr;
            }
        }
    }
}

// ---------------------------------------------------------------------------
// Kernel: permute src ids into dst-sorted order.
// ---------------------------------------------------------------------------
__global__ void edge_scatter_kernel(const int* __restrict__ src,
                                    const int* __restrict__ dst,
                                    int E) {
    int e = (blockIdx.x * blockDim.x + threadIdx.x) * 2;
    if (e + 1 < E) {
        int2 s2 = *(const int2*)(src + e);
        int2 d2 = *(const int2*)(dst + e);
        int r0 = atomicAdd(&g_off[d2.x], 1);
        g_srcs[__ldg(&g_boff[d2.x >> 10]) + r0] = s2.x;
        int r1 = atomicAdd(&g_off[d2.y], 1);
        g_srcs[__ldg(&g_boff[d2.y >> 10]) + r1] = s2.y;
    } else if (e < E) {
        int s = src[e];
        int d = dst[e];
        int r = atomicAdd(&g_off[d], 1);
        g_srcs[__ldg(&g_boff[d >> 10]) + r] = s;
    }
}

// ---------------------------------------------------------------------------
// Kernel: gather aggregation. One warp per dst node (4-wide pipelined).
// fp16 feat gather: 8 B per lane per edge (coalesced 256 B/warp).
// ---------------------------------------------------------------------------
__global__ void __launch_bounds__(256)
aggregate_kernel(const float* __restrict__ bias,
                 float* __restrict__ out,
                 int N) {
    int node = (blockIdx.x * blockDim.x + threadIdx.x) >> 5;
    int lane = threadIdx.x & 31;
    if (node >= N) return;

    int cnt = g_cnt[node];
    int off = g_boff[node >> 10] + g_off[node] - cnt;   // segment start (global)
    int h = lane >> 3;

    float er_h = g_er[node * 4 + h];

    float4 acc = make_float4(0.f, 0.f, 0.f, 0.f);
    float den = 0.f;

    const uint2* feat8 = (const uint2*)g_feat;   // 8 B = 4 halves per lane

    int i = 0;
    for (; i + 4 <= cnt; i += 4) {
        int s0 = g_srcs[off + i + 0];
        int s1 = g_srcs[off + i + 1];
        int s2 = g_srcs[off + i + 2];
        int s3 = g_srcs[off + i + 3];
        float e0 = __ldg(&g_el[s0 * 4 + h]) + er_h;
        float e1 = __ldg(&g_el[s1 * 4 + h]) + er_h;
        float e2 = __ldg(&g_el[s2 * 4 + h]) + er_h;
        float e3 = __ldg(&g_el[s3 * 4 + h]) + er_h;
        uint2 r0 = feat8[(size_t)s0 * 32 + lane];
        uint2 r1 = feat8[(size_t)s1 * 32 + lane];
        uint2 r2 = feat8[(size_t)s2 * 32 + lane];
        uint2 r3 = feat8[(size_t)s3 * 32 + lane];
        e0 = e0 > 0.f ? e0 : NEG_SLOPE * e0;
        e1 = e1 > 0.f ? e1 : NEG_SLOPE * e1;
        e2 = e2 > 0.f ? e2 : NEG_SLOPE * e2;
        e3 = e3 > 0.f ? e3 : NEG_SLOPE * e3;
        float w0 = __expf(e0), w1 = __expf(e1), w2 = __expf(e2), w3 = __expf(e3);
        den += (w0 + w1) + (w2 + w3);
        float2 a0 = __half22float2(*(__half2*)&r0.x);
        float2 b0 = __half22float2(*(__half2*)&r0.y);
        float2 a1 = __half22float2(*(__half2*)&r1.x);
        float2 b1 = __half22float2(*(__half2*)&r1.y);
        float2 a2 = __half22float2(*(__half2*)&r2.x);
        float2 b2 = __half22float2(*(__half2*)&r2.y);
        float2 a3 = __half22float2(*(__half2*)&r3.x);
        float2 b3 = __half22float2(*(__half2*)&r3.y);
        acc.x = fmaf(w0, a0.x, acc.x); acc.y = fmaf(w0, a0.y, acc.y);
        acc.z = fmaf(w0, b0.x, acc.z); acc.w = fmaf(w0, b0.y, acc.w);
        acc.x = fmaf(w1, a1.x, acc.x); acc.y = fmaf(w1, a1.y, acc.y);
        acc.z = fmaf(w1, b1.x, acc.z); acc.w = fmaf(w1, b1.y, acc.w);
        acc.x = fmaf(w2, a2.x, acc.x); acc.y = fmaf(w2, a2.y, acc.y);
        acc.z = fmaf(w2, b2.x, acc.z); acc.w = fmaf(w2, b2.y, acc.w);
        acc.x = fmaf(w3, a3.x, acc.x); acc.y = fmaf(w3, a3.y, acc.y);
        acc.z = fmaf(w3, b3.x, acc.z); acc.w = fmaf(w3, b3.y, acc.w);
    }
    for (; i < cnt; i++) {
        int s0 = g_srcs[off + i];
        float e0 = __ldg(&g_el[s0 * 4 + h]) + er_h;
        e0 = e0 > 0.f ? e0 : NEG_SLOPE * e0;
        float w0 = __expf(e0);
        uint2 r0 = feat8[(size_t)s0 * 32 + lane];
        float2 a0 = __half22float2(*(__half2*)&r0.x);
        float2 b0 = __half22float2(*(__half2*)&r0.y);
        den += w0;
        acc.x = fmaf(w0, a0.x, acc.x); acc.y = fmaf(w0, a0.y, acc.y);
        acc.z = fmaf(w0, b0.x, acc.z); acc.w = fmaf(w0, b0.y, acc.w);
    }

    float inv = __fdividef(1.0f, fmaxf(den, 1e-9f));
    float4 bvec = ((const float4*)bias)[lane];
    acc.x = acc.x * inv + bvec.x;
    acc.y = acc.y * inv + bvec.y;
    acc.z = acc.z * inv + bvec.z;
    acc.w = acc.w * inv + bvec.w;
    acc.x = acc.x > 0.f ? acc.x : expm1f(acc.x);
    acc.y = acc.y > 0.f ? acc.y : expm1f(acc.y);
    acc.z = acc.z > 0.f ? acc.z : expm1f(acc.z);
    acc.w = acc.w > 0.f ? acc.w : expm1f(acc.w);
    __stcs(&((float4*)out)[(size_t)node * 32 + lane], acc);
}

// ---------------------------------------------------------------------------
// Launcher. 2 streams: default = wsplit+gemm, s2 = sort chain.
// Submission order keeps gemm the 4th kernel (ncu profiles slot #4).
// ---------------------------------------------------------------------------
extern "C" void kernel_launch(void* const* d_in, const int* in_sizes, int n_in,
                              void* d_out, int out_size) {
    const float* features = (const float*)d_in[0];
    const int*   src      = (const int*)d_in[1];
    const int*   dst      = (const int*)d_in[2];
    const float* W        = (const float*)d_in[3];
    const float* attn_l   = (const float*)d_in[4];
    const float* attn_r   = (const float*)d_in[5];
    const float* bias     = (const float*)d_in[6];
    float*       out      = (float*)d_out;

    int N = in_sizes[0] / 128;   // 100000
    int E = in_sizes[1];         // 1600000
    int nb = (N + 1023) / 1024;  // scan blocks

    const int GEMM_SMEM = (2 * 64 * ASH + 2 * 128 * WTS) * 2;  // 104448 bytes

    static cudaStream_t s2 = nullptr;
    static cudaEvent_t evFork = nullptr, evJoin = nullptr;
    if (!s2) {
        cudaStreamCreateWithFlags(&s2, cudaStreamNonBlocking);
        cudaEventCreateWithFlags(&evFork, cudaEventDisableTiming);
        cudaEventCreateWithFlags(&evJoin, cudaEventDisableTiming);
        cudaFuncSetAttribute(gemm_kernel, cudaFuncAttributeMaxDynamicSharedMemorySize, GEMM_SMEM);
    }

    // fork side stream from the (capture) default stream
    cudaEventRecord(evFork, 0);
    cudaStreamWaitEvent(s2, evFork, 0);

    // 1 (default): W split (precedes gemm on same stream)
    wsplit_kernel<<<64, 256>>>(W);

    // 2-3 (s2): zero + hist
    zero_kernel<<<(N + 255) / 256, 256, 0, s2>>>(N);
    hist_kernel<<<(E / 4 + 255) / 256, 256, 0, s2>>>(dst, E);

    // 4 (default): fp16-Markidis tensor-core GEMM + fused el/er — ncu slot #4
    gemm_kernel<<<(N + M_TILE - 1) / M_TILE, 256, GEMM_SMEM>>>(features, attn_l, attn_r, N);

    // 5-7 (s2): scanA + scanB + scatter
    scanA_kernel<<<nb, 256, 0, s2>>>(N);
    scanB_kernel<<<1, 128, 0, s2>>>(nb);
    edge_scatter_kernel<<<(E / 2 + 255) / 256, 256, 0, s2>>>(src, dst, E);
    cudaEventRecord(evJoin, s2);

    // join, then aggregate
    cudaStreamWaitEvent(0, evJoin, 0);
    aggregate_kernel<<<(N + 7) / 8, 256>>>(bias, out, N);
}